// round 15
// baseline (speedup 1.0000x reference)
#include <cuda_runtime.h>
#include <cuda_fp16.h>
#include <cstdint>

// Fixed dims: B=4, S=2048 -> M=8192, H=2048, I=8192
#define M_TOK 8192
#define H_DIM 2048
#define I_DIM 8192
#define LN_EPS 1e-6f

// ---------------- scratch (device globals; no allocs) ----------------------
__device__ __half g_Y  [(size_t)M_TOK * H_DIM];       //  33 MB LN out (fp16, k-perm)
__device__ __half g_W1T[(size_t)2 * I_DIM * H_DIM];   //  67 MB W1^T [16384,2048] (k-perm)
__device__ __half g_W2T[(size_t)H_DIM * I_DIM];       //  33 MB W2^T [2048,8192]  (k-perm)
__device__ __half g_Z  [(size_t)M_TOK * I_DIM];       // 134 MB GeGLU out (fp16, k-perm)

// ---------------- helpers --------------------------------------------------
__device__ __forceinline__ float gelu_tanh(float v) {
    float u = 0.7978845608028654f * (v + 0.044715f * v * v * v);
    return 0.5f * v * (1.0f + tanhf(u));
}
// k-permutation within a 32-block; applied to BOTH operands -> result invariant.
__device__ __forceinline__ int p32(int k) {
    return 8 * ((k >> 1) & 3) + 4 * (k >> 4) + 2 * ((k >> 3) & 1) + (k & 1);
}
__device__ __forceinline__ int p32inv(int p) {
    return 16 * ((p >> 2) & 1) + 8 * ((p >> 1) & 1) + 2 * (p >> 3) + (p & 1);
}
__device__ __forceinline__ void cp_async16(void* s, const void* g) {
    unsigned a = (unsigned)__cvta_generic_to_shared(s);
    asm volatile("cp.async.cg.shared.global [%0], [%1], 16;\n" :: "r"(a), "l"(g) : "memory");
}
__device__ __forceinline__ void cp_commit() {
    asm volatile("cp.async.commit_group;\n" ::: "memory");
}
__device__ __forceinline__ void mma_f16(float c[4], uint32_t a0, uint32_t a1,
                                        uint32_t a2, uint32_t a3,
                                        uint32_t b0, uint32_t b1) {
    asm volatile(
        "mma.sync.aligned.m16n8k16.row.col.f32.f16.f16.f32 "
        "{%0,%1,%2,%3}, {%4,%5,%6,%7}, {%8,%9}, {%0,%1,%2,%3};\n"
        : "+f"(c[0]), "+f"(c[1]), "+f"(c[2]), "+f"(c[3])
        : "r"(a0), "r"(a1), "r"(a2), "r"(a3), "r"(b0), "r"(b1));
}

// ---------------- 1) LayerNorm -> Y (fp16, k-permuted cols) ----------------
__global__ void __launch_bounds__(256)
ln_kernel(const float* __restrict__ x, const float* __restrict__ gamma,
          const float* __restrict__ beta, __half* __restrict__ y)
{
    __shared__ float red1[8], red2[8];
    const int row = blockIdx.x, t = threadIdx.x;
    const int lane = t & 31, w = t >> 5;

    const float4* xr = (const float4*)(x + (size_t)row * H_DIM);
    float4 v0 = xr[t], v1 = xr[t + 256];
    float s = v0.x + v0.y + v0.z + v0.w + v1.x + v1.y + v1.z + v1.w;
    #pragma unroll
    for (int o = 16; o > 0; o >>= 1) s += __shfl_xor_sync(0xffffffffu, s, o);
    if (lane == 0) red1[w] = s;
    __syncthreads();
    float tot = 0.f;
    #pragma unroll
    for (int i = 0; i < 8; i++) tot += red1[i];
    const float mu = tot * (1.0f / H_DIM);

    float d[8] = {v0.x - mu, v0.y - mu, v0.z - mu, v0.w - mu,
                  v1.x - mu, v1.y - mu, v1.z - mu, v1.w - mu};
    float ss = 0.f;
    #pragma unroll
    for (int i = 0; i < 8; i++) ss += d[i] * d[i];
    #pragma unroll
    for (int o = 16; o > 0; o >>= 1) ss += __shfl_xor_sync(0xffffffffu, ss, o);
    if (lane == 0) red2[w] = ss;
    __syncthreads();
    float tot2 = 0.f;
    #pragma unroll
    for (int i = 0; i < 8; i++) tot2 += red2[i];
    const float rstd = rsqrtf(tot2 * (1.0f / H_DIM) + LN_EPS);

    const float4* g4 = (const float4*)gamma;
    const float4* b4 = (const float4*)beta;
    __half* yr = y + (size_t)row * H_DIM;

    #pragma unroll
    for (int half_ = 0; half_ < 2; half_++) {
        const int tt = t + half_ * 256;
        float4 ga = g4[tt], ba = b4[tt];
        const float* dd = d + half_ * 4;
        __half h0 = __float2half_rn(dd[0] * rstd * ga.x + ba.x);
        __half h1 = __float2half_rn(dd[1] * rstd * ga.y + ba.y);
        __half h2 = __float2half_rn(dd[2] * rstd * ga.z + ba.z);
        __half h3 = __float2half_rn(dd[3] * rstd * ga.w + ba.w);
        const int base = 32 * (tt >> 3);
        const int off  = 16 * (tt & 1) + 2 * ((tt >> 1) & 1) + 4 * ((tt >> 2) & 1);
        *(__half2*)(yr + base + off)     = __halves2half2(h0, h1);
        *(__half2*)(yr + base + off + 8) = __halves2half2(h2, h3);
    }
}

// ---------------- 2) transpose + fp16 + k-perm -----------------------------
__global__ void __launch_bounds__(256)
transpose_h(const float* __restrict__ in, __half* __restrict__ out, int R, int C)
{
    __shared__ float t[32][33];
    const int bx = blockIdx.x * 32, by = blockIdx.y * 32;
    const int tx = threadIdx.x & 31, ty = threadIdx.x >> 5;
    #pragma unroll
    for (int j = 0; j < 4; j++)
        t[ty + j * 8][tx] = in[(size_t)(by + ty + j * 8) * C + bx + tx];
    __syncthreads();
    const int src = p32inv(tx);
    #pragma unroll
    for (int j = 0; j < 4; j++)
        out[(size_t)(bx + ty + j * 8) * R + by + tx] = __float2half_rn(t[src][ty + j * 8]);
}

// ---------------- 3) fp16 mma.sync GEMM, 64x64 warp tile, 4-stage ----------
// Same geometry as R12 (validated) but the mainloop is explicitly unrolled by
// 4 with LITERAL stage constants, and every iteration commits a (possibly
// empty) cp.async group so wait_group 2 is uniform -> smem addresses fold to
// immediates, per-iter ALU is just the 8 gmem pointer bumps.
#define TILEH (128 * 32)                 // halves per operand tile (8 KB)
#define STG_H (2 * TILEH)                // A+B per stage
#define STAGES 4
#define GEMM_SMEM (STAGES * STG_H * 2)   // 65536 B

template<int G>
__global__ void __launch_bounds__(128, 2)
gemm_h(const __half* __restrict__ A, const __half* __restrict__ Bt,
       void* __restrict__ Cv, int K, int ldc)
{
    extern __shared__ __half sh[];
    const int tid  = threadIdx.x;
    const int lane = tid & 31, wid = tid >> 5;
    const int q = lane >> 2, c = lane & 3;
    const int wm = wid >> 1, wn = wid & 1;

    // m-supertile swizzle (groups of 8 m-tiles) for B-slab L2 reuse
    const int lin = blockIdx.y * gridDim.x + blockIdx.x;
    const int mt_ = (lin / (8 * gridDim.x)) * 8 + (lin % 8);
    const int nt_ = (lin % (8 * gridDim.x)) / 8;
    const int m0  = mt_ * 128;
    const int n0  = nt_ * (G ? 64 : 128);

    float acc[4][8][4];
    #pragma unroll
    for (int i = 0; i < 4; i++)
        #pragma unroll
        for (int j = 0; j < 8; j++)
            #pragma unroll
            for (int p = 0; p < 4; p++) acc[i][j][p] = 0.f;

    const int NK = K >> 5;               // multiple of 4 (64 or 256)

    // cp.async mapping: thread t handles rows (t>>2)+32j, global k-unit (t&3).
    const int rA = tid >> 2, uu = tid & 3;
    const int su = uu ^ (rA & 3);
    const __half* pa[4];
    const __half* pb[4];
    int dst[4];
    #pragma unroll
    for (int j = 0; j < 4; j++) {
        const int row = rA + 32 * j;
        pa[j] = A + (size_t)(m0 + row) * K + uu * 8;
        int brow;
        if (G) brow = (row < 64) ? (n0 + row) : (I_DIM + n0 + row - 64);
        else   brow = n0 + row;
        pb[j] = Bt + (size_t)brow * K + uu * 8;
        dst[j] = row * 32 + su * 8;
    }

    auto load_stage = [&](int s) {       // s is always a literal at call sites
        __half* as = sh + s * STG_H;
        __half* bs = as + TILEH;
        #pragma unroll
        for (int j = 0; j < 4; j++) {
            cp_async16(as + dst[j], pa[j]);
            cp_async16(bs + dst[j], pb[j]);
            pa[j] += 32; pb[j] += 32;
        }
    };

    // prologue: stages 0..2
    load_stage(0); cp_commit();
    load_stage(1); cp_commit();
    load_stage(2); cp_commit();

    const int cba = (c ^ (q & 3)) * 8;
    const int wmb = wm * 64, wnb = wn * (G ? 32 : 64);

    auto compute = [&](const __half* as, const __half* bs) {
        uint4 alo[4], ahi[4];
        #pragma unroll
        for (int mf = 0; mf < 4; ++mf) {
            alo[mf] = *(const uint4*)(as + (wmb + mf * 16 + q)     * 32 + cba);
            ahi[mf] = *(const uint4*)(as + (wmb + mf * 16 + 8 + q) * 32 + cba);
        }
        #pragma unroll
        for (int ug = 0; ug < 2; ++ug) {
            uint4 bb[4];
            #pragma unroll
            for (int j = 0; j < 4; ++j) {
                const int u = ug * 4 + j;
                int brow;
                if (G) brow = (u >> 2) * 64 + wnb + (u & 3) * 8 + q;
                else   brow = wnb + u * 8 + q;
                bb[j] = *(const uint4*)(bs + brow * 32 + cba);
            }
            #pragma unroll
            for (int mf = 0; mf < 4; ++mf)
                #pragma unroll
                for (int j = 0; j < 4; ++j) {
                    const int u = ug * 4 + j;
                    mma_f16(acc[mf][u], alo[mf].x, ahi[mf].x, alo[mf].y, ahi[mf].y,
                            bb[j].x, bb[j].y);
                    mma_f16(acc[mf][u], alo[mf].z, ahi[mf].z, alo[mf].w, ahi[mf].w,
                            bb[j].z, bb[j].w);
                }
        }
    };

    // Mainloop: 4x unrolled, literal stages. Every iter commits one (possibly
    // empty) group => uniform wait_group 2. Invariant: before compute of stage
    // kt, committed = 3+kt groups, <=2 pending => stage kt resident.
#define GITER(KT, S)                                                        \
    {                                                                       \
        asm volatile("cp.async.wait_group 2;\n" ::: "memory");              \
        __syncthreads();                                                    \
        if ((KT) + 3 < NK) load_stage(((S) + 3) & 3);                       \
        cp_commit();                                                        \
        compute(sh + (S) * STG_H, sh + (S) * STG_H + TILEH);                \
    }

    for (int kb = 0; kb < NK; kb += 4) {
        GITER(kb + 0, 0)
        GITER(kb + 1, 1)
        GITER(kb + 2, 2)
        GITER(kb + 3, 3)
    }
#undef GITER

    if (G) {
        // slots 0..3 = gelu branch, 4..7 = linear branch (same I-cols).
        __half* Z = (__half*)Cv;
        #pragma unroll
        for (int mf = 0; mf < 4; ++mf)
            #pragma unroll
            for (int u = 0; u < 4; ++u)
                #pragma unroll
                for (int rr = 0; rr < 2; ++rr) {
                    const int row = m0 + wm * 64 + mf * 16 + rr * 8 + q;
                    const int ic0 = n0 + wn * 32 + u * 8 + 2 * c;
                    const float z0 = gelu_tanh(acc[mf][u][rr * 2 + 0]) *
                                     acc[mf][4 + u][rr * 2 + 0];
                    const float z1 = gelu_tanh(acc[mf][u][rr * 2 + 1]) *
                                     acc[mf][4 + u][rr * 2 + 1];
                    __half* zr = Z + (size_t)row * ldc;
                    *(__half2*)(zr + (ic0 & ~31) + p32(ic0 & 31)) =
                        __halves2half2(__float2half_rn(z0), __float2half_rn(z1));
                }
    } else {
        float* C = (float*)Cv;
        #pragma unroll
        for (int mf = 0; mf < 4; ++mf) {
            const int r = m0 + wm * 64 + mf * 16 + q;
            #pragma unroll
            for (int u = 0; u < 8; ++u) {
                const int cc = n0 + wn * 64 + u * 8 + 2 * c;
                *(float2*)(C + (size_t)r * ldc + cc)       = make_float2(acc[mf][u][0], acc[mf][u][1]);
                *(float2*)(C + (size_t)(r + 8) * ldc + cc) = make_float2(acc[mf][u][2], acc[mf][u][3]);
            }
        }
    }
}

// ---------------- launch ---------------------------------------------------
extern "C" void kernel_launch(void* const* d_in, const int* in_sizes, int n_in,
                              void* d_out, int out_size)
{
    (void)in_sizes; (void)n_in; (void)out_size;
    const float* x     = (const float*)d_in[0];
    const float* gamma = (const float*)d_in[1];
    const float* beta  = (const float*)d_in[2];
    const float* k1    = (const float*)d_in[3];
    const float* k2    = (const float*)d_in[4];
    float* out = (float*)d_out;

    __half *Y, *W1T, *W2T, *Z;
    cudaGetSymbolAddress((void**)&Y,   g_Y);
    cudaGetSymbolAddress((void**)&W1T, g_W1T);
    cudaGetSymbolAddress((void**)&W2T, g_W2T);
    cudaGetSymbolAddress((void**)&Z,   g_Z);

    cudaFuncSetAttribute(gemm_h<1>, cudaFuncAttributeMaxDynamicSharedMemorySize, GEMM_SMEM);
    cudaFuncSetAttribute(gemm_h<0>, cudaFuncAttributeMaxDynamicSharedMemorySize, GEMM_SMEM);

    // 1) LayerNorm -> Y (fp16, k-perm)
    ln_kernel<<<M_TOK, 256>>>(x, gamma, beta, Y);

    // 2) W1 [2048,16384] -> W1T [16384,2048];  W2 [8192,2048] -> W2T [2048,8192]
    transpose_h<<<dim3(16384 / 32, 2048 / 32), 256>>>(k1, W1T, 2048, 16384);
    transpose_h<<<dim3(2048 / 32, 8192 / 32), 256>>>(k2, W2T, 8192, 2048);

    // 3) GEMM1 + fused GeGLU -> Z   (n-tiles = I/64 = 128, m-tiles = 64)
    gemm_h<1><<<dim3(I_DIM / 64, M_TOK / 128), 128, GEMM_SMEM>>>(Y, W1T, Z, H_DIM, I_DIM);

    // 4) GEMM2 -> out              (n-tiles = H/128 = 16, m-tiles = 64)
    gemm_h<0><<<dim3(H_DIM / 128, M_TOK / 128), 128, GEMM_SMEM>>>(Z, W2T, out, I_DIM, H_DIM);
}